// round 14
// baseline (speedup 1.0000x reference)
#include <cuda_runtime.h>

// ---- scratch (static __device__; no allocations allowed) ----
__device__ float g_h1[512*64*128];      // conv1 output   [b][c=64][t=128]
__device__ float g_feats[64*512*128];   // conv2 output   [t'=64][b][in=128]
__device__ float g_wns[64*512*128];     // sensory num    [t'][b][u]
__device__ float g_wds[64*512*128];     // sensory den    [t'][b][u]
__device__ float g_v[512*128];          // persistent LTC state between chunks
__device__ float2 g_sPQ[16384];         // sensory (p,q) folded params
__device__ float  g_sH[16384];          // sensory h2 = 0.5*W*erev
__device__ float2 g_rPQ[16384];         // rec (p,q)
__device__ float  g_rH[16384];          // rec h2
__device__ float  g_hs[512];            // [sens hsum | sens hasum | rec hsum | rec hasum]

__device__ __forceinline__ float fast_tanh(float x){ float y; asm("tanh.approx.f32 %0, %1;" : "=f"(y) : "f"(x)); return y; }
__device__ __forceinline__ float fast_rcp(float x){ float y; asm("rcp.approx.f32 %0, %1;" : "=f"(y) : "f"(x)); return y; }

// ============================================================
// prep: fold params (runs concurrent with conv1 on s2)
// ============================================================
__global__ void __launch_bounds__(256) prep_kernel(
    const float* __restrict__ smu, const float* __restrict__ ssig,
    const float* __restrict__ sW,  const float* __restrict__ serev,
    const float* __restrict__ mu,  const float* __restrict__ sigma,
    const float* __restrict__ W,   const float* __restrict__ erev)
{
    const int stride = gridDim.x * blockDim.x;
    for (int idx = blockIdx.x*blockDim.x + threadIdx.x; idx < 16384; idx += stride){
        float sg = ssig[idx] * 0.5f;
        g_sPQ[idx] = make_float2(sg, -smu[idx] * sg);
        g_sH[idx]  = 0.5f * sW[idx] * serev[idx];
        float rg = sigma[idx] * 0.5f;
        g_rPQ[idx] = make_float2(rg, -mu[idx] * rg);
        g_rH[idx]  = 0.5f * W[idx] * erev[idx];
    }
}

__global__ void __launch_bounds__(128) hsums_kernel()
{
    const int j = threadIdx.x;
    const float* src = blockIdx.x ? g_rH : g_sH;
    const int base = blockIdx.x ? 256 : 0;
    float a = 0.f, bb = 0.f;
    for (int i = 0; i < 128; ++i){ float h = src[(i<<7)+j]; a += h; bb += fabsf(h); }
    g_hs[base + j] = a;
    g_hs[base + 128 + j] = bb;
}

// ============================================================
// conv1: grid 2048 = b x t-quarter; acc[16] -> ~50 regs,
// 4-5 CTAs/SM, fine-grained waves kill the tail waste
// ============================================================
__global__ void __launch_bounds__(256) conv1_kernel(const float* __restrict__ x,
                                                    const float* __restrict__ w,
                                                    const float* __restrict__ bias)
{
    extern __shared__ float sm[];
    float* xs = sm;               // [24][72], col tl -> global t = q*64 - 2 + tl
    float* ws = sm + 24*72;       // [(f*5+k)][64]
    float* bs = ws + 7680;        // [64]
    const int b = blockIdx.x >> 2, q = blockIdx.x & 3;
    const int tid = threadIdx.x;
    const int t0 = q * 64;

    for (int idx = tid; idx < 24*68; idx += 256){
        int tl = idx / 24, f = idx % 24;
        int tg = t0 - 2 + tl;
        xs[f*72 + tl] = (tg >= 0 && tg < 256) ? x[b*6144 + tg*24 + f] : 0.f;
    }
    for (int idx = tid; idx < 7680; idx += 256){
        int c = idx / 120, r = idx % 120;   // r = f*5+k
        ws[r*64 + c] = w[idx];
    }
    if (tid < 64) bs[tid] = bias[tid];
    __syncthreads();

    const int c = tid & 63, seg = tid >> 6;   // 4 segs x 16 pre-pool t
    const float bv = bs[c];
    float acc[16];
    #pragma unroll
    for (int jj = 0; jj < 16; ++jj) acc[jj] = 0.f;
    for (int f = 0; f < 24; ++f){
        float wr[5];
        #pragma unroll
        for (int k = 0; k < 5; ++k) wr[k] = ws[(f*5+k)*64 + c];
        float xr[20];
        #pragma unroll
        for (int ii = 0; ii < 20; ++ii) xr[ii] = xs[f*72 + seg*16 + ii];
        #pragma unroll
        for (int jj = 0; jj < 16; ++jj){
            float a = acc[jj];
            #pragma unroll
            for (int k = 0; k < 5; ++k) a = fmaf(wr[k], xr[jj+k], a);
            acc[jj] = a;
        }
    }
    const int tp0 = q*32 + seg*8;
    #pragma unroll
    for (int m = 0; m < 8; ++m){
        float v = fmaxf(fmaxf(acc[2*m], acc[2*m+1]) + bv, 0.f);
        g_h1[(b*64 + c)*128 + tp0 + m] = v;
    }
}

// ============================================================
// conv2: co-quarters (32 co each); grid = 512 b * 4 quarters
// (at practical floor ~120us; frozen)
// ============================================================
__global__ void __launch_bounds__(256) conv2_kernel(const float* __restrict__ w,
                                                    const float* __restrict__ bias)
{
    extern __shared__ float sm[];
    float* xs = sm;                 // [64][130], col = t+1 (pad 1 each side)
    float* ws = xs + 64*130;        // [(cin*3+k)][32]
    float* bs = ws + 6144;          // [32]
    const int b = blockIdx.x >> 2, quarter = blockIdx.x & 3;
    const int tid = threadIdx.x;
    const int co_base = quarter * 32;

    for (int idx = tid; idx < 8192; idx += 256){
        int cin = idx >> 7, t = idx & 127;
        xs[cin*130 + t + 1] = g_h1[b*8192 + idx];
    }
    for (int idx = tid; idx < 6144; idx += 256){
        int co = idx / 192, r = idx % 192;  // r = cin*3+k
        ws[r*32 + co] = w[(co_base + co)*192 + r];
    }
    if (tid < 32) bs[tid] = bias[co_base + tid];
    if (tid < 128){ int cin = tid >> 1, p = tid & 1; xs[cin*130 + (p ? 129 : 0)] = 0.f; }
    __syncthreads();

    const int co = tid & 31, seg = tid >> 5;   // 8 segs x 16 pre-pool t
    const float bv = bs[co];
    const int tbase = seg*16;
    float acc[16];
    #pragma unroll
    for (int jj = 0; jj < 16; ++jj) acc[jj] = 0.f;
    for (int cin = 0; cin < 64; ++cin){
        float wr[3];
        #pragma unroll
        for (int k = 0; k < 3; ++k) wr[k] = ws[(cin*3+k)*32 + co];
        float xr[18];
        #pragma unroll
        for (int ii = 0; ii < 18; ++ii) xr[ii] = xs[cin*130 + tbase + ii];
        #pragma unroll
        for (int jj = 0; jj < 16; ++jj){
            float a = acc[jj];
            #pragma unroll
            for (int k = 0; k < 3; ++k) a = fmaf(wr[k], xr[jj+k], a);
            acc[jj] = a;
        }
    }
    const int co_g = co_base + co;
    const int tp0 = seg*8;
    #pragma unroll
    for (int m = 0; m < 8; ++m){
        float v = fmaxf(fmaxf(acc[2*m], acc[2*m+1]) + bv, 0.f);
        g_feats[((tp0 + m)*512 + b)*128 + co_g] = v;
    }
}

// ============================================================
// sensory (chunked): quads g in [0,nquads), pair base = tbeg*512 + g*4
// ============================================================
__global__ void __launch_bounds__(512) sensory_kernel(
    int tbeg, int nquads,
    const float* __restrict__ iw, const float* __restrict__ ib)
{
    extern __shared__ float sm[];
    float2* sPQ = (float2*)sm;         // [16384]
    float*  sH  = sm + 32768;          // [16384]
    float*  xts = sH + 16384;          // [4][128]
    float*  pn  = xts + 512;           // [4 qt][4 pair][128]
    float*  pd  = pn + 2048;           // [4 qt][4 pair][128]
    float*  siw = pd + 2048;           // [128]
    float*  sib = siw + 128;           // [128]
    const int tid = threadIdx.x;

    for (int idx = tid; idx < 16384; idx += 512){
        sPQ[idx] = g_sPQ[idx];
        sH[idx]  = g_sH[idx];
    }
    if (tid < 128){ siw[tid] = iw[tid]; sib[tid] = ib[tid]; }
    __syncthreads();

    const int j = tid & 127, qt = tid >> 7;
    const int i0 = qt << 5;
    const float hs = g_hs[j], has = g_hs[128 + j];
    const int sp = tid >> 7, si = tid & 127;
    const int pair0 = tbeg * 512;

    for (int g = blockIdx.x; g < nquads; g += gridDim.x){
        const int qbase = pair0 + g*4;
        xts[tid] = fmaf(g_feats[(qbase+sp)*128 + si], siw[si], sib[si]);
        __syncthreads();

        float n[4] = {0.f,0.f,0.f,0.f}, d[4] = {0.f,0.f,0.f,0.f};
        #pragma unroll 4
        for (int ii = 0; ii < 32; ii += 4){
            const int i = i0 + ii;
            float4 x0 = *(const float4*)&xts[i];
            float4 x1 = *(const float4*)&xts[128+i];
            float4 x2 = *(const float4*)&xts[256+i];
            float4 x3 = *(const float4*)&xts[384+i];
            const float xv[4][4] = {{x0.x,x1.x,x2.x,x3.x},{x0.y,x1.y,x2.y,x3.y},
                                    {x0.z,x1.z,x2.z,x3.z},{x0.w,x1.w,x2.w,x3.w}};
            #pragma unroll
            for (int k = 0; k < 4; ++k){
                float2 P = sPQ[((i+k)<<7) + j];
                float h  = sH[((i+k)<<7) + j];
                float ha = fabsf(h);
                #pragma unroll
                for (int r = 0; r < 4; ++r){
                    float tt = fast_tanh(fmaf(xv[k][r], P.x, P.y));
                    n[r] = fmaf(h, tt, n[r]);
                    d[r] = fmaf(ha, tt, d[r]);
                }
            }
        }
        #pragma unroll
        for (int r = 0; r < 4; ++r){
            pn[(qt*4+r)*128 + j] = n[r];
            pd[(qt*4+r)*128 + j] = d[r];
        }
        __syncthreads();
        {
            float sn = pn[(0*4+qt)*128+j] + pn[(1*4+qt)*128+j] + pn[(2*4+qt)*128+j] + pn[(3*4+qt)*128+j];
            float sd = pd[(0*4+qt)*128+j] + pd[(1*4+qt)*128+j] + pd[(2*4+qt)*128+j] + pd[(3*4+qt)*128+j];
            g_wns[(qbase+qt)*128 + j] = sn + hs;
            g_wds[(qbase+qt)*128 + j] = sd + has;
        }
        __syncthreads();
    }
}

// ============================================================
// LTC recurrence chunk [tbeg, tend); fused MLP head when tend==64
// ============================================================
__global__ void __launch_bounds__(512) rec_kernel(
    int tbeg, int tend, int zeroInit,
    const float* __restrict__ vleak, const float* __restrict__ gleak,
    const float* __restrict__ cmt,
    const float* __restrict__ fc1w, const float* __restrict__ fc1b,
    const float* __restrict__ fc2w, const float* __restrict__ fc2b,
    float* __restrict__ out)
{
    extern __shared__ float sm[];
    float2* rPQ = (float2*)sm;         // [16384]
    float*  rH  = sm + 32768;          // [16384]
    float*  sV  = rH + 16384;          // [4][128]
    float*  pn  = sV + 512;            // [4 qt][4 row][128]
    float*  pd  = pn + 2048;           // [4 qt][4 row][128]
    const int tid = threadIdx.x;
    const int bbase = blockIdx.x * 4;

    for (int idx = tid; idx < 16384; idx += 512){
        rPQ[idx] = g_rPQ[idx];
        rH[idx]  = g_rH[idx];
    }
    sV[tid] = zeroInit ? 0.f : g_v[(bbase + (tid>>7))*128 + (tid & 127)];
    __syncthreads();

    const int j = tid & 127, qt = tid >> 7;
    const int i0 = qt << 5;
    const float cmv = cmt[j];
    const float gl  = gleak[j];
    const float base_n = gl * vleak[j] + g_hs[256 + j];
    const float base_d = cmv + gl + g_hs[384 + j];

    for (int t = tbeg; t < tend; ++t){
        const int q = (t*512 + bbase + qt)*128 + j;
        const float c_n = base_n + g_wns[q];
        const float c_d = base_d + g_wds[q];
        for (int u = 0; u < 6; ++u){
            float n[4] = {0.f,0.f,0.f,0.f}, d[4] = {0.f,0.f,0.f,0.f};
            #pragma unroll 4
            for (int ii = 0; ii < 32; ii += 4){
                const int i = i0 + ii;
                float4 v0 = *(const float4*)&sV[i];
                float4 v1 = *(const float4*)&sV[128+i];
                float4 v2 = *(const float4*)&sV[256+i];
                float4 v3 = *(const float4*)&sV[384+i];
                const float vv[4][4] = {{v0.x,v1.x,v2.x,v3.x},{v0.y,v1.y,v2.y,v3.y},
                                        {v0.z,v1.z,v2.z,v3.z},{v0.w,v1.w,v2.w,v3.w}};
                #pragma unroll
                for (int k = 0; k < 4; ++k){
                    float2 P = rPQ[((i+k)<<7) + j];
                    float h  = rH[((i+k)<<7) + j];
                    float ha = fabsf(h);
                    #pragma unroll
                    for (int r = 0; r < 4; ++r){
                        float tt = fast_tanh(fmaf(vv[k][r], P.x, P.y));
                        n[r] = fmaf(h, tt, n[r]);
                        d[r] = fmaf(ha, tt, d[r]);
                    }
                }
            }
            #pragma unroll
            for (int r = 0; r < 4; ++r){
                pn[(qt*4+r)*128 + j] = n[r];
                pd[(qt*4+r)*128 + j] = d[r];
            }
            __syncthreads();
            {
                float sn = pn[(0*4+qt)*128+j] + pn[(1*4+qt)*128+j] + pn[(2*4+qt)*128+j] + pn[(3*4+qt)*128+j];
                float sd = pd[(0*4+qt)*128+j] + pd[(1*4+qt)*128+j] + pd[(2*4+qt)*128+j] + pd[(3*4+qt)*128+j];
                float vold = sV[qt*128 + j];
                float nv = (fmaf(cmv, vold, c_n) + sn) * fast_rcp(c_d + sd);
                __syncthreads();
                sV[qt*128 + j] = nv;
            }
            __syncthreads();
        }
    }

    if (tend < 64){
        g_v[(bbase + qt)*128 + j] = sV[qt*128 + j];
    } else {
        // fused head: 64 threads per row compute relu(fc1.v+b1)*fc2, reduce
        const int d2 = tid & 127;
        if (d2 < 64){
            float acc = fc1b[d2];
            const float* vrow = sV + qt*128;
            #pragma unroll 16
            for (int k = 0; k < 128; ++k)
                acc = fmaf(fc1w[d2*128 + k], vrow[k], acc);
            acc = fmaxf(acc, 0.f) * fc2w[d2];
            #pragma unroll
            for (int off = 16; off > 0; off >>= 1)
                acc += __shfl_down_sync(0xffffffffu, acc, off);
            if ((d2 & 31) == 0) pn[qt*2 + (d2 >> 5)] = acc;
        }
        __syncthreads();
        if (d2 == 0) out[bbase + qt] = pn[qt*2] + pn[qt*2 + 1] + fc2b[0];
    }
}

extern "C" void kernel_launch(void* const* d_in, const int* in_sizes, int n_in,
                              void* d_out, int out_size)
{
    const float* x     = (const float*)d_in[0];
    const float* c1w   = (const float*)d_in[1];
    const float* c1b   = (const float*)d_in[2];
    const float* c2w   = (const float*)d_in[3];
    const float* c2b   = (const float*)d_in[4];
    const float* iw    = (const float*)d_in[5];
    const float* ib    = (const float*)d_in[6];
    const float* smu   = (const float*)d_in[7];
    const float* ssig  = (const float*)d_in[8];
    const float* sW    = (const float*)d_in[9];
    const float* serev = (const float*)d_in[10];
    const float* mu    = (const float*)d_in[11];
    const float* sigma = (const float*)d_in[12];
    const float* W     = (const float*)d_in[13];
    const float* erev  = (const float*)d_in[14];
    const float* vleak = (const float*)d_in[15];
    const float* gleak = (const float*)d_in[16];
    const float* cmt   = (const float*)d_in[17];
    const float* fc1w  = (const float*)d_in[18];
    const float* fc1b  = (const float*)d_in[19];
    const float* fc2w  = (const float*)d_in[20];
    const float* fc2b  = (const float*)d_in[21];
    float* out = (float*)d_out;

    const int SM_C1 = (24*72 + 7680 + 64) * 4;                          //  37,888 B
    const int SM_C2 = (64*130 + 6144 + 32) * 4;                         //  57,984 B
    const int SM_SE = (32768 + 16384 + 512 + 2048 + 2048 + 256) * 4;    // 216,064 B
    const int SM_RE = (32768 + 16384 + 512 + 2048 + 2048) * 4;          // 215,040 B

    static bool inited = false;
    static cudaStream_t s2;
    static cudaEvent_t evStart, evPrep, evFork, evChunk[5];
    if (!inited){
        cudaStreamCreate(&s2);
        cudaEventCreateWithFlags(&evStart, cudaEventDisableTiming);
        cudaEventCreateWithFlags(&evPrep,  cudaEventDisableTiming);
        cudaEventCreateWithFlags(&evFork,  cudaEventDisableTiming);
        for (int k = 0; k < 5; ++k)
            cudaEventCreateWithFlags(&evChunk[k], cudaEventDisableTiming);
        cudaFuncSetAttribute(conv1_kernel,   cudaFuncAttributeMaxDynamicSharedMemorySize, SM_C1);
        cudaFuncSetAttribute(conv2_kernel,   cudaFuncAttributeMaxDynamicSharedMemorySize, SM_C2);
        cudaFuncSetAttribute(sensory_kernel, cudaFuncAttributeMaxDynamicSharedMemorySize, SM_SE);
        cudaFuncSetAttribute(rec_kernel,     cudaFuncAttributeMaxDynamicSharedMemorySize, SM_RE);
        inited = true;
    }

    // fork s2 from the capture-origin stream BEFORE launching on it
    cudaEventRecord(evStart, 0);
    cudaStreamWaitEvent(s2, evStart, 0);

    // param prep on s2, concurrent with convs
    prep_kernel<<<128, 256, 0, s2>>>(smu, ssig, sW, serev, mu, sigma, W, erev);
    hsums_kernel<<<2, 128, 0, s2>>>();
    cudaEventRecord(evPrep, s2);

    conv1_kernel<<<2048, 256, SM_C1>>>(x, c1w, c1b);
    conv2_kernel<<<2048, 256, SM_C2>>>(c2w, c2b);

    // sensory runway: t in [0, 24) on the full chip
    cudaStreamWaitEvent(0, evPrep, 0);
    sensory_kernel<<<148, 512, SM_SE>>>(0, 24*128, iw, ib);

    // fork: remaining sensory chunks (8 t each) on 20 CTAs, concurrent with rec
    cudaEventRecord(evFork, 0);
    cudaStreamWaitEvent(s2, evFork, 0);
    for (int k = 0; k < 5; ++k){
        sensory_kernel<<<20, 512, SM_SE, s2>>>(24 + 8*k, 8*128, iw, ib);
        cudaEventRecord(evChunk[k], s2);
    }

    // rec chunks on the main stream
    rec_kernel<<<128, 512, SM_RE>>>(0, 24, 1, vleak, gleak, cmt, fc1w, fc1b, fc2w, fc2b, out);
    for (int k = 0; k < 5; ++k){
        cudaStreamWaitEvent(0, evChunk[k], 0);
        rec_kernel<<<128, 512, SM_RE>>>(24 + 8*k, 32 + 8*k, 0, vleak, gleak, cmt, fc1w, fc1b, fc2w, fc2b, out);
    }
}

// round 15
// speedup vs baseline: 1.0049x; 1.0049x over previous
#include <cuda_runtime.h>

// ---- scratch (static __device__; no allocations allowed) ----
__device__ float g_h1[512*64*128];      // conv1 output   [b][c=64][t=128]
__device__ float g_feats[64*512*128];   // conv2 output   [t'=64][b][in=128]
__device__ float g_wns[64*512*128];     // sensory num    [t'][b][u]
__device__ float g_wds[64*512*128];     // sensory den    [t'][b][u]
__device__ float g_v[512*128];          // persistent LTC state between chunks
__device__ float2 g_sPQ[16384];         // sensory (p,q) folded params
__device__ float  g_sH[16384];          // sensory h2 = 0.5*W*erev
__device__ float2 g_rPQ[16384];         // rec (p,q)
__device__ float  g_rH[16384];          // rec h2
__device__ float  g_hs[512];            // [sens hsum | sens hasum | rec hsum | rec hasum]

__device__ __forceinline__ float fast_tanh(float x){ float y; asm("tanh.approx.f32 %0, %1;" : "=f"(y) : "f"(x)); return y; }
__device__ __forceinline__ float fast_rcp(float x){ float y; asm("rcp.approx.f32 %0, %1;" : "=f"(y) : "f"(x)); return y; }

// ============================================================
// prep: fold params (runs concurrent with conv1 on s2)
// ============================================================
__global__ void __launch_bounds__(256) prep_kernel(
    const float* __restrict__ smu, const float* __restrict__ ssig,
    const float* __restrict__ sW,  const float* __restrict__ serev,
    const float* __restrict__ mu,  const float* __restrict__ sigma,
    const float* __restrict__ W,   const float* __restrict__ erev)
{
    const int stride = gridDim.x * blockDim.x;
    for (int idx = blockIdx.x*blockDim.x + threadIdx.x; idx < 16384; idx += stride){
        float sg = ssig[idx] * 0.5f;
        g_sPQ[idx] = make_float2(sg, -smu[idx] * sg);
        g_sH[idx]  = 0.5f * sW[idx] * serev[idx];
        float rg = sigma[idx] * 0.5f;
        g_rPQ[idx] = make_float2(rg, -mu[idx] * rg);
        g_rH[idx]  = 0.5f * W[idx] * erev[idx];
    }
}

__global__ void __launch_bounds__(128) hsums_kernel()
{
    const int j = threadIdx.x;
    const float* src = blockIdx.x ? g_rH : g_sH;
    const int base = blockIdx.x ? 256 : 0;
    float a = 0.f, bb = 0.f;
    for (int i = 0; i < 128; ++i){ float h = src[(i<<7)+j]; a += h; bb += fabsf(h); }
    g_hs[base + j] = a;
    g_hs[base + 128 + j] = bb;
}

// ============================================================
// conv1: grid 1024 = b x t-half; scalar FMA (R7 proven form)
// ============================================================
__global__ void __launch_bounds__(256) conv1_kernel(const float* __restrict__ x,
                                                    const float* __restrict__ w,
                                                    const float* __restrict__ bias)
{
    extern __shared__ float sm[];
    float* xs = sm;               // [24][136], col = t_g - half*128 + 2
    float* ws = sm + 24*136;      // [(f*5+k)][64]
    float* bs = ws + 7680;        // [64]
    const int b = blockIdx.x >> 1, half = blockIdx.x & 1;
    const int tid = threadIdx.x;
    const int t0 = half * 128;

    for (int idx = tid; idx < 24*132; idx += 256){
        int tl = idx / 24, f = idx % 24;
        int tg = t0 - 2 + tl;
        xs[f*136 + tl] = (tg >= 0 && tg < 256) ? x[b*6144 + tg*24 + f] : 0.f;
    }
    for (int idx = tid; idx < 7680; idx += 256){
        int c = idx / 120, r = idx % 120;   // r = f*5+k
        ws[r*64 + c] = w[idx];
    }
    if (tid < 64) bs[tid] = bias[tid];
    __syncthreads();

    const int c = tid & 63, seg = tid >> 6;   // 4 segs x 32 pre-pool t
    const float bv = bs[c];
    float acc[32];
    #pragma unroll
    for (int jj = 0; jj < 32; ++jj) acc[jj] = 0.f;
    for (int f = 0; f < 24; ++f){
        float wr[5];
        #pragma unroll
        for (int k = 0; k < 5; ++k) wr[k] = ws[(f*5+k)*64 + c];
        float xr[36];
        #pragma unroll
        for (int ii = 0; ii < 36; ++ii) xr[ii] = xs[f*136 + seg*32 + ii];
        #pragma unroll
        for (int jj = 0; jj < 32; ++jj){
            float a = acc[jj];
            #pragma unroll
            for (int k = 0; k < 5; ++k) a = fmaf(wr[k], xr[jj+k], a);
            acc[jj] = a;
        }
    }
    const int tp0 = half*64 + seg*16;
    #pragma unroll
    for (int m = 0; m < 16; ++m){
        float v = fmaxf(fmaxf(acc[2*m], acc[2*m+1]) + bv, 0.f);
        g_h1[(b*64 + c)*128 + tp0 + m] = v;
    }
}

// ============================================================
// conv2: co-quarters (32 co each); grid = 512 b * 4 quarters
// (at practical floor ~120us; frozen)
// ============================================================
__global__ void __launch_bounds__(256) conv2_kernel(const float* __restrict__ w,
                                                    const float* __restrict__ bias)
{
    extern __shared__ float sm[];
    float* xs = sm;                 // [64][130], col = t+1 (pad 1 each side)
    float* ws = xs + 64*130;        // [(cin*3+k)][32]
    float* bs = ws + 6144;          // [32]
    const int b = blockIdx.x >> 2, quarter = blockIdx.x & 3;
    const int tid = threadIdx.x;
    const int co_base = quarter * 32;

    for (int idx = tid; idx < 8192; idx += 256){
        int cin = idx >> 7, t = idx & 127;
        xs[cin*130 + t + 1] = g_h1[b*8192 + idx];
    }
    for (int idx = tid; idx < 6144; idx += 256){
        int co = idx / 192, r = idx % 192;  // r = cin*3+k
        ws[r*32 + co] = w[(co_base + co)*192 + r];
    }
    if (tid < 32) bs[tid] = bias[co_base + tid];
    if (tid < 128){ int cin = tid >> 1, p = tid & 1; xs[cin*130 + (p ? 129 : 0)] = 0.f; }
    __syncthreads();

    const int co = tid & 31, seg = tid >> 5;   // 8 segs x 16 pre-pool t
    const float bv = bs[co];
    const int tbase = seg*16;
    float acc[16];
    #pragma unroll
    for (int jj = 0; jj < 16; ++jj) acc[jj] = 0.f;
    for (int cin = 0; cin < 64; ++cin){
        float wr[3];
        #pragma unroll
        for (int k = 0; k < 3; ++k) wr[k] = ws[(cin*3+k)*32 + co];
        float xr[18];
        #pragma unroll
        for (int ii = 0; ii < 18; ++ii) xr[ii] = xs[cin*130 + tbase + ii];
        #pragma unroll
        for (int jj = 0; jj < 16; ++jj){
            float a = acc[jj];
            #pragma unroll
            for (int k = 0; k < 3; ++k) a = fmaf(wr[k], xr[jj+k], a);
            acc[jj] = a;
        }
    }
    const int co_g = co_base + co;
    const int tp0 = seg*8;
    #pragma unroll
    for (int m = 0; m < 8; ++m){
        float v = fmaxf(fmaxf(acc[2*m], acc[2*m+1]) + bv, 0.f);
        g_feats[((tp0 + m)*512 + b)*128 + co_g] = v;
    }
}

// ============================================================
// sensory (chunked): quads g in [0,nquads), pair base = tbeg*512 + g*4
// ============================================================
__global__ void __launch_bounds__(512) sensory_kernel(
    int tbeg, int nquads,
    const float* __restrict__ iw, const float* __restrict__ ib)
{
    extern __shared__ float sm[];
    float2* sPQ = (float2*)sm;         // [16384]
    float*  sH  = sm + 32768;          // [16384]
    float*  xts = sH + 16384;          // [4][128]
    float*  pn  = xts + 512;           // [4 qt][4 pair][128]
    float*  pd  = pn + 2048;           // [4 qt][4 pair][128]
    float*  siw = pd + 2048;           // [128]
    float*  sib = siw + 128;           // [128]
    const int tid = threadIdx.x;

    for (int idx = tid; idx < 16384; idx += 512){
        sPQ[idx] = g_sPQ[idx];
        sH[idx]  = g_sH[idx];
    }
    if (tid < 128){ siw[tid] = iw[tid]; sib[tid] = ib[tid]; }
    __syncthreads();

    const int j = tid & 127, qt = tid >> 7;
    const int i0 = qt << 5;
    const float hs = g_hs[j], has = g_hs[128 + j];
    const int sp = tid >> 7, si = tid & 127;
    const int pair0 = tbeg * 512;

    for (int g = blockIdx.x; g < nquads; g += gridDim.x){
        const int qbase = pair0 + g*4;
        xts[tid] = fmaf(g_feats[(qbase+sp)*128 + si], siw[si], sib[si]);
        __syncthreads();

        float n[4] = {0.f,0.f,0.f,0.f}, d[4] = {0.f,0.f,0.f,0.f};
        #pragma unroll 4
        for (int ii = 0; ii < 32; ii += 4){
            const int i = i0 + ii;
            float4 x0 = *(const float4*)&xts[i];
            float4 x1 = *(const float4*)&xts[128+i];
            float4 x2 = *(const float4*)&xts[256+i];
            float4 x3 = *(const float4*)&xts[384+i];
            const float xv[4][4] = {{x0.x,x1.x,x2.x,x3.x},{x0.y,x1.y,x2.y,x3.y},
                                    {x0.z,x1.z,x2.z,x3.z},{x0.w,x1.w,x2.w,x3.w}};
            #pragma unroll
            for (int k = 0; k < 4; ++k){
                float2 P = sPQ[((i+k)<<7) + j];
                float h  = sH[((i+k)<<7) + j];
                float ha = fabsf(h);
                #pragma unroll
                for (int r = 0; r < 4; ++r){
                    float tt = fast_tanh(fmaf(xv[k][r], P.x, P.y));
                    n[r] = fmaf(h, tt, n[r]);
                    d[r] = fmaf(ha, tt, d[r]);
                }
            }
        }
        #pragma unroll
        for (int r = 0; r < 4; ++r){
            pn[(qt*4+r)*128 + j] = n[r];
            pd[(qt*4+r)*128 + j] = d[r];
        }
        __syncthreads();
        {
            float sn = pn[(0*4+qt)*128+j] + pn[(1*4+qt)*128+j] + pn[(2*4+qt)*128+j] + pn[(3*4+qt)*128+j];
            float sd = pd[(0*4+qt)*128+j] + pd[(1*4+qt)*128+j] + pd[(2*4+qt)*128+j] + pd[(3*4+qt)*128+j];
            g_wns[(qbase+qt)*128 + j] = sn + hs;
            g_wds[(qbase+qt)*128 + j] = sd + has;
        }
        __syncthreads();
    }
}

// ============================================================
// LTC recurrence chunk [tbeg, tend); fused MLP head when tend==64
// ============================================================
__global__ void __launch_bounds__(512) rec_kernel(
    int tbeg, int tend, int zeroInit,
    const float* __restrict__ vleak, const float* __restrict__ gleak,
    const float* __restrict__ cmt,
    const float* __restrict__ fc1w, const float* __restrict__ fc1b,
    const float* __restrict__ fc2w, const float* __restrict__ fc2b,
    float* __restrict__ out)
{
    extern __shared__ float sm[];
    float2* rPQ = (float2*)sm;         // [16384]
    float*  rH  = sm + 32768;          // [16384]
    float*  sV  = rH + 16384;          // [4][128]
    float*  pn  = sV + 512;            // [4 qt][4 row][128]
    float*  pd  = pn + 2048;           // [4 qt][4 row][128]
    const int tid = threadIdx.x;
    const int bbase = blockIdx.x * 4;

    for (int idx = tid; idx < 16384; idx += 512){
        rPQ[idx] = g_rPQ[idx];
        rH[idx]  = g_rH[idx];
    }
    sV[tid] = zeroInit ? 0.f : g_v[(bbase + (tid>>7))*128 + (tid & 127)];
    __syncthreads();

    const int j = tid & 127, qt = tid >> 7;
    const int i0 = qt << 5;
    const float cmv = cmt[j];
    const float gl  = gleak[j];
    const float base_n = gl * vleak[j] + g_hs[256 + j];
    const float base_d = cmv + gl + g_hs[384 + j];

    for (int t = tbeg; t < tend; ++t){
        const int q = (t*512 + bbase + qt)*128 + j;
        const float c_n = base_n + g_wns[q];
        const float c_d = base_d + g_wds[q];
        for (int u = 0; u < 6; ++u){
            float n[4] = {0.f,0.f,0.f,0.f}, d[4] = {0.f,0.f,0.f,0.f};
            #pragma unroll 4
            for (int ii = 0; ii < 32; ii += 4){
                const int i = i0 + ii;
                float4 v0 = *(const float4*)&sV[i];
                float4 v1 = *(const float4*)&sV[128+i];
                float4 v2 = *(const float4*)&sV[256+i];
                float4 v3 = *(const float4*)&sV[384+i];
                const float vv[4][4] = {{v0.x,v1.x,v2.x,v3.x},{v0.y,v1.y,v2.y,v3.y},
                                        {v0.z,v1.z,v2.z,v3.z},{v0.w,v1.w,v2.w,v3.w}};
                #pragma unroll
                for (int k = 0; k < 4; ++k){
                    float2 P = rPQ[((i+k)<<7) + j];
                    float h  = rH[((i+k)<<7) + j];
                    float ha = fabsf(h);
                    #pragma unroll
                    for (int r = 0; r < 4; ++r){
                        float tt = fast_tanh(fmaf(vv[k][r], P.x, P.y));
                        n[r] = fmaf(h, tt, n[r]);
                        d[r] = fmaf(ha, tt, d[r]);
                    }
                }
            }
            #pragma unroll
            for (int r = 0; r < 4; ++r){
                pn[(qt*4+r)*128 + j] = n[r];
                pd[(qt*4+r)*128 + j] = d[r];
            }
            __syncthreads();
            {
                float sn = pn[(0*4+qt)*128+j] + pn[(1*4+qt)*128+j] + pn[(2*4+qt)*128+j] + pn[(3*4+qt)*128+j];
                float sd = pd[(0*4+qt)*128+j] + pd[(1*4+qt)*128+j] + pd[(2*4+qt)*128+j] + pd[(3*4+qt)*128+j];
                float vold = sV[qt*128 + j];
                float nv = (fmaf(cmv, vold, c_n) + sn) * fast_rcp(c_d + sd);
                __syncthreads();
                sV[qt*128 + j] = nv;
            }
            __syncthreads();
        }
    }

    if (tend < 64){
        g_v[(bbase + qt)*128 + j] = sV[qt*128 + j];
    } else {
        // fused head: 64 threads per row compute relu(fc1.v+b1)*fc2, reduce
        const int d2 = tid & 127;
        if (d2 < 64){
            float acc = fc1b[d2];
            const float* vrow = sV + qt*128;
            #pragma unroll 16
            for (int k = 0; k < 128; ++k)
                acc = fmaf(fc1w[d2*128 + k], vrow[k], acc);
            acc = fmaxf(acc, 0.f) * fc2w[d2];
            #pragma unroll
            for (int off = 16; off > 0; off >>= 1)
                acc += __shfl_down_sync(0xffffffffu, acc, off);
            if ((d2 & 31) == 0) pn[qt*2 + (d2 >> 5)] = acc;
        }
        __syncthreads();
        if (d2 == 0) out[bbase + qt] = pn[qt*2] + pn[qt*2 + 1] + fc2b[0];
    }
}

extern "C" void kernel_launch(void* const* d_in, const int* in_sizes, int n_in,
                              void* d_out, int out_size)
{
    const float* x     = (const float*)d_in[0];
    const float* c1w   = (const float*)d_in[1];
    const float* c1b   = (const float*)d_in[2];
    const float* c2w   = (const float*)d_in[3];
    const float* c2b   = (const float*)d_in[4];
    const float* iw    = (const float*)d_in[5];
    const float* ib    = (const float*)d_in[6];
    const float* smu   = (const float*)d_in[7];
    const float* ssig  = (const float*)d_in[8];
    const float* sW    = (const float*)d_in[9];
    const float* serev = (const float*)d_in[10];
    const float* mu    = (const float*)d_in[11];
    const float* sigma = (const float*)d_in[12];
    const float* W     = (const float*)d_in[13];
    const float* erev  = (const float*)d_in[14];
    const float* vleak = (const float*)d_in[15];
    const float* gleak = (const float*)d_in[16];
    const float* cmt   = (const float*)d_in[17];
    const float* fc1w  = (const float*)d_in[18];
    const float* fc1b  = (const float*)d_in[19];
    const float* fc2w  = (const float*)d_in[20];
    const float* fc2b  = (const float*)d_in[21];
    float* out = (float*)d_out;

    const int SM_C1 = (24*136 + 7680 + 64) * 4;                         //  44,032 B
    const int SM_C2 = (64*130 + 6144 + 32) * 4;                         //  57,984 B
    const int SM_SE = (32768 + 16384 + 512 + 2048 + 2048 + 256) * 4;    // 216,064 B
    const int SM_RE = (32768 + 16384 + 512 + 2048 + 2048) * 4;          // 215,040 B

    static bool inited = false;
    static cudaStream_t s2;
    static cudaEvent_t evStart, evPrep, evFork, evChunk[8];
    if (!inited){
        cudaStreamCreate(&s2);
        cudaEventCreateWithFlags(&evStart, cudaEventDisableTiming);
        cudaEventCreateWithFlags(&evPrep,  cudaEventDisableTiming);
        cudaEventCreateWithFlags(&evFork,  cudaEventDisableTiming);
        for (int k = 0; k < 8; ++k)
            cudaEventCreateWithFlags(&evChunk[k], cudaEventDisableTiming);
        cudaFuncSetAttribute(conv1_kernel,   cudaFuncAttributeMaxDynamicSharedMemorySize, SM_C1);
        cudaFuncSetAttribute(conv2_kernel,   cudaFuncAttributeMaxDynamicSharedMemorySize, SM_C2);
        cudaFuncSetAttribute(sensory_kernel, cudaFuncAttributeMaxDynamicSharedMemorySize, SM_SE);
        cudaFuncSetAttribute(rec_kernel,     cudaFuncAttributeMaxDynamicSharedMemorySize, SM_RE);
        inited = true;
    }

    // fork s2 from the capture-origin stream BEFORE launching on it
    cudaEventRecord(evStart, 0);
    cudaStreamWaitEvent(s2, evStart, 0);

    // param prep on s2, concurrent with convs
    prep_kernel<<<128, 256, 0, s2>>>(smu, ssig, sW, serev, mu, sigma, W, erev);
    hsums_kernel<<<2, 128, 0, s2>>>();
    cudaEventRecord(evPrep, s2);

    conv1_kernel<<<1024, 256, SM_C1>>>(x, c1w, c1b);
    conv2_kernel<<<2048, 256, SM_C2>>>(c2w, c2b);

    // sensory runway: t in [0, 24) on the full chip
    cudaStreamWaitEvent(0, evPrep, 0);
    sensory_kernel<<<148, 512, SM_SE>>>(0, 24*128, iw, ib);

    // fork: remaining sensory in 8 chunks of 5 t each on 20 CTAs,
    // concurrent with rec (zero-stall schedule)
    cudaEventRecord(evFork, 0);
    cudaStreamWaitEvent(s2, evFork, 0);
    for (int k = 0; k < 8; ++k){
        sensory_kernel<<<20, 512, SM_SE, s2>>>(24 + 5*k, 5*128, iw, ib);
        cudaEventRecord(evChunk[k], s2);
    }

    // rec chunks on the main stream
    rec_kernel<<<128, 512, SM_RE>>>(0, 24, 1, vleak, gleak, cmt, fc1w, fc1b, fc2w, fc2b, out);
    for (int k = 0; k < 8; ++k){
        cudaStreamWaitEvent(0, evChunk[k], 0);
        rec_kernel<<<128, 512, SM_RE>>>(24 + 5*k, 29 + 5*k, 0, vleak, gleak, cmt, fc1w, fc1b, fc2w, fc2b, out);
    }
}

// round 16
// speedup vs baseline: 1.0199x; 1.0149x over previous
#include <cuda_runtime.h>

// ---- scratch (static __device__; no allocations allowed) ----
__device__ float g_h1[512*64*128];      // conv1 output   [b][c=64][t=128]
__device__ float g_feats[64*512*128];   // conv2 output   [t'=64][b][in=128]
__device__ float g_wns[64*512*128];     // sensory num    [t'][b][u]
__device__ float g_wds[64*512*128];     // sensory den    [t'][b][u]
__device__ float g_v[512*128];          // persistent LTC state between chunks
__device__ float2 g_sPQ[16384];         // sensory (p,q) folded params
__device__ float  g_sH[16384];          // sensory h2 = 0.5*W*erev
__device__ float2 g_rPQ[16384];         // rec (p,q)
__device__ float  g_rH[16384];          // rec h2
__device__ float  g_hs[512];            // [sens hsum | sens hasum | rec hsum | rec hasum]

__device__ __forceinline__ float fast_tanh(float x){ float y; asm("tanh.approx.f32 %0, %1;" : "=f"(y) : "f"(x)); return y; }
__device__ __forceinline__ float fast_rcp(float x){ float y; asm("rcp.approx.f32 %0, %1;" : "=f"(y) : "f"(x)); return y; }

// ============================================================
// prep: fold params (runs concurrent with conv1 on s2)
// ============================================================
__global__ void __launch_bounds__(256) prep_kernel(
    const float* __restrict__ smu, const float* __restrict__ ssig,
    const float* __restrict__ sW,  const float* __restrict__ serev,
    const float* __restrict__ mu,  const float* __restrict__ sigma,
    const float* __restrict__ W,   const float* __restrict__ erev)
{
    const int stride = gridDim.x * blockDim.x;
    for (int idx = blockIdx.x*blockDim.x + threadIdx.x; idx < 16384; idx += stride){
        float sg = ssig[idx] * 0.5f;
        g_sPQ[idx] = make_float2(sg, -smu[idx] * sg);
        g_sH[idx]  = 0.5f * sW[idx] * serev[idx];
        float rg = sigma[idx] * 0.5f;
        g_rPQ[idx] = make_float2(rg, -mu[idx] * rg);
        g_rH[idx]  = 0.5f * W[idx] * erev[idx];
    }
}

__global__ void __launch_bounds__(128) hsums_kernel()
{
    const int j = threadIdx.x;
    const float* src = blockIdx.x ? g_rH : g_sH;
    const int base = blockIdx.x ? 256 : 0;
    float a = 0.f, bb = 0.f;
    for (int i = 0; i < 128; ++i){ float h = src[(i<<7)+j]; a += h; bb += fabsf(h); }
    g_hs[base + j] = a;
    g_hs[base + 128 + j] = bb;
}

// ============================================================
// conv1: grid 1024 = b x t-half; scalar FMA (R7 proven form)
// ============================================================
__global__ void __launch_bounds__(256) conv1_kernel(const float* __restrict__ x,
                                                    const float* __restrict__ w,
                                                    const float* __restrict__ bias)
{
    extern __shared__ float sm[];
    float* xs = sm;               // [24][136], col = t_g - half*128 + 2
    float* ws = sm + 24*136;      // [(f*5+k)][64]
    float* bs = ws + 7680;        // [64]
    const int b = blockIdx.x >> 1, half = blockIdx.x & 1;
    const int tid = threadIdx.x;
    const int t0 = half * 128;

    for (int idx = tid; idx < 24*132; idx += 256){
        int tl = idx / 24, f = idx % 24;
        int tg = t0 - 2 + tl;
        xs[f*136 + tl] = (tg >= 0 && tg < 256) ? x[b*6144 + tg*24 + f] : 0.f;
    }
    for (int idx = tid; idx < 7680; idx += 256){
        int c = idx / 120, r = idx % 120;   // r = f*5+k
        ws[r*64 + c] = w[idx];
    }
    if (tid < 64) bs[tid] = bias[tid];
    __syncthreads();

    const int c = tid & 63, seg = tid >> 6;   // 4 segs x 32 pre-pool t
    const float bv = bs[c];
    float acc[32];
    #pragma unroll
    for (int jj = 0; jj < 32; ++jj) acc[jj] = 0.f;
    for (int f = 0; f < 24; ++f){
        float wr[5];
        #pragma unroll
        for (int k = 0; k < 5; ++k) wr[k] = ws[(f*5+k)*64 + c];
        float xr[36];
        #pragma unroll
        for (int ii = 0; ii < 36; ++ii) xr[ii] = xs[f*136 + seg*32 + ii];
        #pragma unroll
        for (int jj = 0; jj < 32; ++jj){
            float a = acc[jj];
            #pragma unroll
            for (int k = 0; k < 5; ++k) a = fmaf(wr[k], xr[jj+k], a);
            acc[jj] = a;
        }
    }
    const int tp0 = half*64 + seg*16;
    #pragma unroll
    for (int m = 0; m < 16; ++m){
        float v = fmaxf(fmaxf(acc[2*m], acc[2*m+1]) + bv, 0.f);
        g_h1[(b*64 + c)*128 + tp0 + m] = v;
    }
}

// ============================================================
// conv2: co-quarters (32 co each); grid = 512 b * 4 quarters
// ============================================================
__global__ void __launch_bounds__(256) conv2_kernel(const float* __restrict__ w,
                                                    const float* __restrict__ bias)
{
    extern __shared__ float sm[];
    float* xs = sm;                 // [64][130], col = t+1 (pad 1 each side)
    float* ws = xs + 64*130;        // [(cin*3+k)][32]
    float* bs = ws + 6144;          // [32]
    const int b = blockIdx.x >> 2, quarter = blockIdx.x & 3;
    const int tid = threadIdx.x;
    const int co_base = quarter * 32;

    for (int idx = tid; idx < 8192; idx += 256){
        int cin = idx >> 7, t = idx & 127;
        xs[cin*130 + t + 1] = g_h1[b*8192 + idx];
    }
    for (int idx = tid; idx < 6144; idx += 256){
        int co = idx / 192, r = idx % 192;  // r = cin*3+k
        ws[r*32 + co] = w[(co_base + co)*192 + r];
    }
    if (tid < 32) bs[tid] = bias[co_base + tid];
    if (tid < 128){ int cin = tid >> 1, p = tid & 1; xs[cin*130 + (p ? 129 : 0)] = 0.f; }
    __syncthreads();

    const int co = tid & 31, seg = tid >> 5;   // 8 segs x 16 pre-pool t
    const float bv = bs[co];
    const int tbase = seg*16;
    float acc[16];
    #pragma unroll
    for (int jj = 0; jj < 16; ++jj) acc[jj] = 0.f;
    for (int cin = 0; cin < 64; ++cin){
        float wr[3];
        #pragma unroll
        for (int k = 0; k < 3; ++k) wr[k] = ws[(cin*3+k)*32 + co];
        float xr[18];
        #pragma unroll
        for (int ii = 0; ii < 18; ++ii) xr[ii] = xs[cin*130 + tbase + ii];
        #pragma unroll
        for (int jj = 0; jj < 16; ++jj){
            float a = acc[jj];
            #pragma unroll
            for (int k = 0; k < 3; ++k) a = fmaf(wr[k], xr[jj+k], a);
            acc[jj] = a;
        }
    }
    const int co_g = co_base + co;
    const int tp0 = seg*8;
    #pragma unroll
    for (int m = 0; m < 8; ++m){
        float v = fmaxf(fmaxf(acc[2*m], acc[2*m+1]) + bv, 0.f);
        g_feats[((tp0 + m)*512 + b)*128 + co_g] = v;
    }
}

// ============================================================
// sensory (chunked): quads g in [0,nquads), pair base = tbeg*512 + g*4
// ============================================================
__global__ void __launch_bounds__(512) sensory_kernel(
    int tbeg, int nquads,
    const float* __restrict__ iw, const float* __restrict__ ib)
{
    extern __shared__ float sm[];
    float2* sPQ = (float2*)sm;         // [16384]
    float*  sH  = sm + 32768;          // [16384]
    float*  xts = sH + 16384;          // [4][128]
    float*  pn  = xts + 512;           // [4 qt][4 pair][128]
    float*  pd  = pn + 2048;           // [4 qt][4 pair][128]
    float*  siw = pd + 2048;           // [128]
    float*  sib = siw + 128;           // [128]
    const int tid = threadIdx.x;

    for (int idx = tid; idx < 16384; idx += 512){
        sPQ[idx] = g_sPQ[idx];
        sH[idx]  = g_sH[idx];
    }
    if (tid < 128){ siw[tid] = iw[tid]; sib[tid] = ib[tid]; }
    __syncthreads();

    const int j = tid & 127, qt = tid >> 7;
    const int i0 = qt << 5;
    const float hs = g_hs[j], has = g_hs[128 + j];
    const int sp = tid >> 7, si = tid & 127;
    const int pair0 = tbeg * 512;

    for (int g = blockIdx.x; g < nquads; g += gridDim.x){
        const int qbase = pair0 + g*4;
        xts[tid] = fmaf(g_feats[(qbase+sp)*128 + si], siw[si], sib[si]);
        __syncthreads();

        float n[4] = {0.f,0.f,0.f,0.f}, d[4] = {0.f,0.f,0.f,0.f};
        #pragma unroll 4
        for (int ii = 0; ii < 32; ii += 4){
            const int i = i0 + ii;
            float4 x0 = *(const float4*)&xts[i];
            float4 x1 = *(const float4*)&xts[128+i];
            float4 x2 = *(const float4*)&xts[256+i];
            float4 x3 = *(const float4*)&xts[384+i];
            const float xv[4][4] = {{x0.x,x1.x,x2.x,x3.x},{x0.y,x1.y,x2.y,x3.y},
                                    {x0.z,x1.z,x2.z,x3.z},{x0.w,x1.w,x2.w,x3.w}};
            #pragma unroll
            for (int k = 0; k < 4; ++k){
                float2 P = sPQ[((i+k)<<7) + j];
                float h  = sH[((i+k)<<7) + j];
                float ha = fabsf(h);
                #pragma unroll
                for (int r = 0; r < 4; ++r){
                    float tt = fast_tanh(fmaf(xv[k][r], P.x, P.y));
                    n[r] = fmaf(h, tt, n[r]);
                    d[r] = fmaf(ha, tt, d[r]);
                }
            }
        }
        #pragma unroll
        for (int r = 0; r < 4; ++r){
            pn[(qt*4+r)*128 + j] = n[r];
            pd[(qt*4+r)*128 + j] = d[r];
        }
        __syncthreads();
        {
            float sn = pn[(0*4+qt)*128+j] + pn[(1*4+qt)*128+j] + pn[(2*4+qt)*128+j] + pn[(3*4+qt)*128+j];
            float sd = pd[(0*4+qt)*128+j] + pd[(1*4+qt)*128+j] + pd[(2*4+qt)*128+j] + pd[(3*4+qt)*128+j];
            g_wns[(qbase+qt)*128 + j] = sn + hs;
            g_wds[(qbase+qt)*128 + j] = sd + has;
        }
        __syncthreads();
    }
}

// ============================================================
// LTC recurrence chunk [tbeg, tend); fused MLP head when tend==64
// ============================================================
__global__ void __launch_bounds__(512) rec_kernel(
    int tbeg, int tend, int zeroInit,
    const float* __restrict__ vleak, const float* __restrict__ gleak,
    const float* __restrict__ cmt,
    const float* __restrict__ fc1w, const float* __restrict__ fc1b,
    const float* __restrict__ fc2w, const float* __restrict__ fc2b,
    float* __restrict__ out)
{
    extern __shared__ float sm[];
    float2* rPQ = (float2*)sm;         // [16384]
    float*  rH  = sm + 32768;          // [16384]
    float*  sV  = rH + 16384;          // [4][128]
    float*  pn  = sV + 512;            // [4 qt][4 row][128]
    float*  pd  = pn + 2048;           // [4 qt][4 row][128]
    const int tid = threadIdx.x;
    const int bbase = blockIdx.x * 4;

    for (int idx = tid; idx < 16384; idx += 512){
        rPQ[idx] = g_rPQ[idx];
        rH[idx]  = g_rH[idx];
    }
    sV[tid] = zeroInit ? 0.f : g_v[(bbase + (tid>>7))*128 + (tid & 127)];
    __syncthreads();

    const int j = tid & 127, qt = tid >> 7;
    const int i0 = qt << 5;
    const float cmv = cmt[j];
    const float gl  = gleak[j];
    const float base_n = gl * vleak[j] + g_hs[256 + j];
    const float base_d = cmv + gl + g_hs[384 + j];

    for (int t = tbeg; t < tend; ++t){
        const int q = (t*512 + bbase + qt)*128 + j;
        const float c_n = base_n + g_wns[q];
        const float c_d = base_d + g_wds[q];
        for (int u = 0; u < 6; ++u){
            float n[4] = {0.f,0.f,0.f,0.f}, d[4] = {0.f,0.f,0.f,0.f};
            #pragma unroll 4
            for (int ii = 0; ii < 32; ii += 4){
                const int i = i0 + ii;
                float4 v0 = *(const float4*)&sV[i];
                float4 v1 = *(const float4*)&sV[128+i];
                float4 v2 = *(const float4*)&sV[256+i];
                float4 v3 = *(const float4*)&sV[384+i];
                const float vv[4][4] = {{v0.x,v1.x,v2.x,v3.x},{v0.y,v1.y,v2.y,v3.y},
                                        {v0.z,v1.z,v2.z,v3.z},{v0.w,v1.w,v2.w,v3.w}};
                #pragma unroll
                for (int k = 0; k < 4; ++k){
                    float2 P = rPQ[((i+k)<<7) + j];
                    float h  = rH[((i+k)<<7) + j];
                    float ha = fabsf(h);
                    #pragma unroll
                    for (int r = 0; r < 4; ++r){
                        float tt = fast_tanh(fmaf(vv[k][r], P.x, P.y));
                        n[r] = fmaf(h, tt, n[r]);
                        d[r] = fmaf(ha, tt, d[r]);
                    }
                }
            }
            #pragma unroll
            for (int r = 0; r < 4; ++r){
                pn[(qt*4+r)*128 + j] = n[r];
                pd[(qt*4+r)*128 + j] = d[r];
            }
            __syncthreads();
            {
                float sn = pn[(0*4+qt)*128+j] + pn[(1*4+qt)*128+j] + pn[(2*4+qt)*128+j] + pn[(3*4+qt)*128+j];
                float sd = pd[(0*4+qt)*128+j] + pd[(1*4+qt)*128+j] + pd[(2*4+qt)*128+j] + pd[(3*4+qt)*128+j];
                float vold = sV[qt*128 + j];
                float nv = (fmaf(cmv, vold, c_n) + sn) * fast_rcp(c_d + sd);
                __syncthreads();
                sV[qt*128 + j] = nv;
            }
            __syncthreads();
        }
    }

    if (tend < 64){
        g_v[(bbase + qt)*128 + j] = sV[qt*128 + j];
    } else {
        // fused head: 64 threads per row compute relu(fc1.v+b1)*fc2, reduce
        const int d2 = tid & 127;
        if (d2 < 64){
            float acc = fc1b[d2];
            const float* vrow = sV + qt*128;
            #pragma unroll 16
            for (int k = 0; k < 128; ++k)
                acc = fmaf(fc1w[d2*128 + k], vrow[k], acc);
            acc = fmaxf(acc, 0.f) * fc2w[d2];
            #pragma unroll
            for (int off = 16; off > 0; off >>= 1)
                acc += __shfl_down_sync(0xffffffffu, acc, off);
            if ((d2 & 31) == 0) pn[qt*2 + (d2 >> 5)] = acc;
        }
        __syncthreads();
        if (d2 == 0) out[bbase + qt] = pn[qt*2] + pn[qt*2 + 1] + fc2b[0];
    }
}

extern "C" void kernel_launch(void* const* d_in, const int* in_sizes, int n_in,
                              void* d_out, int out_size)
{
    const float* x     = (const float*)d_in[0];
    const float* c1w   = (const float*)d_in[1];
    const float* c1b   = (const float*)d_in[2];
    const float* c2w   = (const float*)d_in[3];
    const float* c2b   = (const float*)d_in[4];
    const float* iw    = (const float*)d_in[5];
    const float* ib    = (const float*)d_in[6];
    const float* smu   = (const float*)d_in[7];
    const float* ssig  = (const float*)d_in[8];
    const float* sW    = (const float*)d_in[9];
    const float* serev = (const float*)d_in[10];
    const float* mu    = (const float*)d_in[11];
    const float* sigma = (const float*)d_in[12];
    const float* W     = (const float*)d_in[13];
    const float* erev  = (const float*)d_in[14];
    const float* vleak = (const float*)d_in[15];
    const float* gleak = (const float*)d_in[16];
    const float* cmt   = (const float*)d_in[17];
    const float* fc1w  = (const float*)d_in[18];
    const float* fc1b  = (const float*)d_in[19];
    const float* fc2w  = (const float*)d_in[20];
    const float* fc2b  = (const float*)d_in[21];
    float* out = (float*)d_out;

    const int SM_C1 = (24*136 + 7680 + 64) * 4;                         //  44,032 B
    const int SM_C2 = (64*130 + 6144 + 32) * 4;                         //  57,984 B
    const int SM_SE = (32768 + 16384 + 512 + 2048 + 2048 + 256) * 4;    // 216,064 B
    const int SM_RE = (32768 + 16384 + 512 + 2048 + 2048) * 4;          // 215,040 B

    static bool inited = false;
    static cudaStream_t s2;
    static cudaEvent_t evStart, evPrep, evFork, evChunk[4];
    if (!inited){
        cudaStreamCreate(&s2);
        cudaEventCreateWithFlags(&evStart, cudaEventDisableTiming);
        cudaEventCreateWithFlags(&evPrep,  cudaEventDisableTiming);
        cudaEventCreateWithFlags(&evFork,  cudaEventDisableTiming);
        for (int k = 0; k < 4; ++k)
            cudaEventCreateWithFlags(&evChunk[k], cudaEventDisableTiming);
        cudaFuncSetAttribute(conv1_kernel,   cudaFuncAttributeMaxDynamicSharedMemorySize, SM_C1);
        cudaFuncSetAttribute(conv2_kernel,   cudaFuncAttributeMaxDynamicSharedMemorySize, SM_C2);
        cudaFuncSetAttribute(sensory_kernel, cudaFuncAttributeMaxDynamicSharedMemorySize, SM_SE);
        cudaFuncSetAttribute(rec_kernel,     cudaFuncAttributeMaxDynamicSharedMemorySize, SM_RE);
        inited = true;
    }

    // fork s2 from the capture-origin stream BEFORE launching on it
    cudaEventRecord(evStart, 0);
    cudaStreamWaitEvent(s2, evStart, 0);

    // param prep on s2, concurrent with convs
    prep_kernel<<<128, 256, 0, s2>>>(smu, ssig, sW, serev, mu, sigma, W, erev);
    hsums_kernel<<<2, 128, 0, s2>>>();
    cudaEventRecord(evPrep, s2);

    conv1_kernel<<<1024, 256, SM_C1>>>(x, c1w, c1b);
    conv2_kernel<<<2048, 256, SM_C2>>>(c2w, c2b);

    // sensory runway: t in [0, 24) on the full chip
    cudaStreamWaitEvent(0, evPrep, 0);
    sensory_kernel<<<148, 512, SM_SE>>>(0, 24*128, iw, ib);

    // fork: remaining sensory in 4 chunks of 10 t each on 20 CTAs,
    // concurrent with rec (zero-stall, minimal reloads)
    cudaEventRecord(evFork, 0);
    cudaStreamWaitEvent(s2, evFork, 0);
    for (int k = 0; k < 4; ++k){
        sensory_kernel<<<20, 512, SM_SE, s2>>>(24 + 10*k, 10*128, iw, ib);
        cudaEventRecord(evChunk[k], s2);
    }

    // rec chunks on the main stream
    rec_kernel<<<128, 512, SM_RE>>>(0, 24, 1, vleak, gleak, cmt, fc1w, fc1b, fc2w, fc2b, out);
    for (int k = 0; k < 4; ++k){
        cudaStreamWaitEvent(0, evChunk[k], 0);
        rec_kernel<<<128, 512, SM_RE>>>(24 + 10*k, 34 + 10*k, 0, vleak, gleak, cmt, fc1w, fc1b, fc2w, fc2b, out);
    }
}